// round 4
// baseline (speedup 1.0000x reference)
#include <cuda_runtime.h>
#include <cuda_bf16.h>
#include <cstdint>

// Problem constants
#define BS     2
#define NM     10
#define NA     8400
#define NC     80
#define NPT    360
#define NBINS  36
#define NBM    (BS*NM)
#define BSNMNA (BS*NM*NA)
#define BSNA   (BS*NA)
#define MAXL   1024

// Output layout (flat float32, reference tuple order)
#define TL_OFF      0
#define TB_OFF      16800
#define TS_OFF      84000
#define MPB_OFF     1428000
#define TGI_OFF     1596000
#define GTDIST_OFF  1612800
#define CENT_OFF    7660800
#define FG_OFF      7828800
#define OUT_TOTAL   7845600

// Scratch. Written at live entries only; read at positive entries (pos ⊆ live).
// g_cnt is re-zeroed at the end of k_scores (per-bm block), g_topkbits at the
// end of k_assign (per-thread slot) -> state identical at the start of every
// replay (globals are zero-initialized at load).
__device__ float g_align[BSNMNA];
__device__ float g_overlaps[BSNMNA];
__device__ float g_cent[BSNMNA];
__device__ __align__(16) float g_dist[(size_t)BSNMNA * NBINS];
__device__ int   g_liveA[NBM * MAXL];
__device__ int   g_cnt[NBM];
__device__ unsigned g_inbits[BSNA];
__device__ unsigned g_topkbits[BSNA];
__device__ unsigned g_finbits[BSNA];

__device__ __forceinline__ unsigned long long ullmax2(unsigned long long a, unsigned long long b){ return a>b?a:b; }

// ---------------------------------------------------------------------------
// K1: per-anchor in-box bitmask + per-GT compacted live lists
// ---------------------------------------------------------------------------
__global__ __launch_bounds__(256) void k_compact(
    const float* __restrict__ anc,
    const float* __restrict__ gt_bboxes,
    const float* __restrict__ mask_gt)
{
    __shared__ float sbox[NBM][4];
    __shared__ float smgt[NBM];
    if (threadIdx.x < NBM) {
        sbox[threadIdx.x][0] = gt_bboxes[threadIdx.x*4+0];
        sbox[threadIdx.x][1] = gt_bboxes[threadIdx.x*4+1];
        sbox[threadIdx.x][2] = gt_bboxes[threadIdx.x*4+2];
        sbox[threadIdx.x][3] = gt_bboxes[threadIdx.x*4+3];
        smgt[threadIdx.x] = mask_gt[threadIdx.x];
    }
    __syncthreads();
    int t = blockIdx.x * blockDim.x + threadIdx.x;
    if (t >= BSNA) return;
    int b = t / NA, a = t % NA;
    float ax = anc[2*a], ay = anc[2*a+1];
    unsigned inb = 0;
    #pragma unroll
    for (int m = 0; m < NM; m++) {
        int bm = b*NM + m;
        if (smgt[bm] == 0.f) continue;
        float mind = fminf(fminf(ax - sbox[bm][0], ay - sbox[bm][1]),
                           fminf(sbox[bm][2] - ax, sbox[bm][3] - ay));
        if (mind > 1e-9f) {
            inb |= (1u << m);
            int s = atomicAdd(&g_cnt[bm], 1);
            if (s < MAXL) g_liveA[bm*MAXL + s] = a;
        }
    }
    g_inbits[t] = inb;
}

// ---------------------------------------------------------------------------
// K2: heavy per-pair work on live pairs, bucketed angle bins
// ---------------------------------------------------------------------------
__global__ __launch_bounds__(128) void k_pairs(
    const float* __restrict__ pd_scores,
    const float* __restrict__ pd_bboxes,
    const float* __restrict__ anc,
    const int*   __restrict__ gt_labels,
    const float* __restrict__ gt_coor)
{
    int bm = blockIdx.y;
    int cnt = g_cnt[bm];
    if (cnt == 0) return;
    if (cnt > MAXL) cnt = MAXL;
    int b = bm / NM;

    __shared__ float sx[NPT], sy[NPT], sdist[NPT], sang[NPT];
    __shared__ unsigned short sidx[NPT];
    __shared__ unsigned char sbk[NPT];
    __shared__ int scnt[NBINS], soff[NBINS], scur[NBINS];
    __shared__ float sdm[NBINS];

    const float* gp = gt_coor + (size_t)bm * (2*NPT);
    for (int p = threadIdx.x; p < NPT; p += blockDim.x) {
        sx[p] = gp[2*p];
        sy[p] = gp[2*p+1];
    }
    int label = gt_labels[bm];
    __syncthreads();

    int tid = threadIdx.x;
    int lane = tid & 31;
    int warp = tid >> 5;

    for (int j = blockIdx.x; j < cnt; j += gridDim.x) {
        int a = g_liveA[bm*MAXL + j];
        float ax = anc[2*a], ay = anc[2*a+1];
        int pairIdx = bm * NA + a;

        if (tid < NBINS) scnt[tid] = 0;
        __syncthreads();

        // point phase: distance + angle + bucket count
        for (int p = tid; p < NPT; p += 128) {
            float dx = sx[p] - ax, dy = sy[p] - ay;
            sdist[p] = sqrtf(dx*dx + dy*dy);
            float ang = atan2f(dy, dx) * 57.29577951308232f;
            if (ang < 0.f) ang += 360.f;
            sang[p] = ang;
            int bk = (int)(ang * 0.1f);
            if (bk > 35) bk = 35;
            sbk[p] = (unsigned char)bk;
            atomicAdd(&scnt[bk], 1);
        }
        __syncthreads();

        // exclusive scan of 36 counts (warp 0)
        if (tid < 32) {
            int orig = scnt[lane];
            int c = orig;
            #pragma unroll
            for (int off = 1; off < 32; off <<= 1) {
                int n = __shfl_up_sync(0xffffffffu, c, off);
                if (lane >= off) c += n;
            }
            int excl = c - orig;
            soff[lane] = excl; scur[lane] = excl;
            int tot32 = __shfl_sync(0xffffffffu, c, 31);
            if (lane < 4) {
                int e = tot32;
                for (int q = 0; q < lane; q++) e += scnt[32+q];
                soff[32+lane] = e; scur[32+lane] = e;
            }
        }
        __syncthreads();

        // scatter point ids into CSR buckets
        for (int p = tid; p < NPT; p += 128) {
            int pos = atomicAdd(&scur[sbk[p]], 1);
            sidx[pos] = (unsigned short)p;
        }
        __syncthreads();

        // bin phase: one thread per bin, expanding bucket rings
        if (tid < NBINS) {
            float th = (float)(tid * 10);
            unsigned long long k0=~0ull,k1=~0ull,k2=~0ull,k3=~0ull;
            int nseen = 0;
            for (int L = 0; L < 18; L++) {
                int bA = tid - 1 - L; if (bA < 0) bA += NBINS;
                int bB = tid + L;     if (bB >= NBINS) bB -= NBINS;
                #pragma unroll
                for (int side = 0; side < 2; side++) {
                    int bkt = side ? bB : bA;
                    int s = soff[bkt], n = scnt[bkt];
                    for (int i = 0; i < n; i++) {
                        int p = sidx[s + i];
                        float df = fabsf(sang[p] - th);
                        if (df > 180.f) df = 360.f - df;
                        unsigned long long key =
                            ((unsigned long long)__float_as_uint(df) << 32) | (unsigned)p;
                        nseen++;
                        if (key < k3) {
                            k3 = key;
                            unsigned long long tmp;
                            if (k3 < k2) { tmp=k2; k2=k3; k3=tmp; }
                            if (k2 < k1) { tmp=k1; k1=k2; k2=tmp; }
                            if (k1 < k0) { tmp=k0; k0=k1; k1=tmp; }
                        }
                    }
                }
                if (nseen >= 4) break;
            }
            float mindiff = __uint_as_float((unsigned)(k0 >> 32));
            float dmax = sdist[(unsigned)(k0 & 0xffffffffu)];
            dmax = fmaxf(dmax, sdist[(unsigned)(k1 & 0xffffffffu)]);
            dmax = fmaxf(dmax, sdist[(unsigned)(k2 & 0xffffffffu)]);
            dmax = fmaxf(dmax, sdist[(unsigned)(k3 & 0xffffffffu)]);
            float dm = (mindiff > 3.0f) ? 1e-6f : dmax;
            dm = fmaxf(dm, 1e-6f);
            sdm[tid] = dm;
            g_dist[(size_t)pairIdx * NBINS + tid] = dm;
        }
        __syncthreads();

        // warp 0 epilogue: iou + centerness + align metric
        if (warp == 0) {
            float smin = 0.f, smax = 0.f, mn = 1e30f, mx = 0.f;
            const float* pb = pd_bboxes + ((size_t)b*NA + a) * NBINS;
            for (int e = lane; e < NBINS; e += 32) {
                float t = sdm[e], p = pb[e];
                smin += fmaxf(fminf(t, p), 1e-6f);
                smax += fmaxf(t, p);
                mn = fminf(mn, t);
                mx = fmaxf(mx, t);
            }
            #pragma unroll
            for (int off = 16; off; off >>= 1) {
                smin += __shfl_xor_sync(0xffffffffu, smin, off);
                smax += __shfl_xor_sync(0xffffffffu, smax, off);
                mn = fminf(mn, __shfl_xor_sync(0xffffffffu, mn, off));
                mx = fmaxf(mx, __shfl_xor_sync(0xffffffffu, mx, off));
            }
            if (lane == 0) {
                float iou = smin / smax;
                float score = pd_scores[((size_t)b*NA + a) * NC + label];
                g_overlaps[pairIdx] = iou;
                g_align[pairIdx]    = score * iou * iou * iou;
                g_cent[pairIdx]     = sqrtf(mn / mx);
            }
        }
        __syncthreads();
    }
}

// ---------------------------------------------------------------------------
// K3: top-13 per GT, single warp, no block barriers
// ---------------------------------------------------------------------------
__global__ __launch_bounds__(32) void k_topk(const float* __restrict__ mask_gt) {
    int bm = blockIdx.x;
    if (mask_gt[bm] == 0.f) return;
    int cnt = g_cnt[bm];
    if (cnt == 0) return;
    if (cnt > MAXL) cnt = MAXL;
    int lane = threadIdx.x;

    __shared__ unsigned long long sk[MAXL];
    const int* la = g_liveA + bm*MAXL;
    for (int j = lane; j < cnt; j += 32) {
        int a = la[j];
        float v = g_align[bm*NA + a];
        sk[j] = ((unsigned long long)__float_as_uint(v) << 32) | (unsigned)(NA - a);
    }
    __syncwarp();

    int b = bm / NM, m = bm % NM;
    int kmax = cnt < 13 ? cnt : 13;
    for (int k = 0; k < kmax; k++) {
        unsigned long long best = 0;
        for (int j = lane; j < cnt; j += 32) best = ullmax2(best, sk[j]);
        #pragma unroll
        for (int off = 16; off; off >>= 1)
            best = ullmax2(best, __shfl_xor_sync(0xffffffffu, best, off));
        if (best == 0) break;   // padding picks carry mask_pos=0 in reference
        for (int j = lane; j < cnt; j += 32) if (sk[j] == best) sk[j] = 0;
        if (lane == 0) {
            int a = NA - (int)(best & 0xffffffffu);
            atomicOr(&g_topkbits[b*NA + a], 1u << m);
        }
        __syncwarp();
    }
}

// ---------------------------------------------------------------------------
// K4: per-anchor resolution + most outputs; recycles g_topkbits to zero
// ---------------------------------------------------------------------------
__global__ __launch_bounds__(256) void k_assign(
    const int*   __restrict__ gt_labels,
    const float* __restrict__ gt_bboxes,
    float* __restrict__ out)
{
    int t = blockIdx.x * blockDim.x + threadIdx.x;
    if (t >= BSNA) return;
    int b = t / NA, a = t % NA;

    unsigned tb = g_topkbits[t];
    g_topkbits[t] = 0u;                 // reset for next replay
    unsigned fin = tb;
    if (__popc(tb) > 1) {
        unsigned inb = g_inbits[t];
        float best = -1.f; int bi = 0;
        #pragma unroll
        for (int m = 0; m < NM; m++) {
            float o = ((inb >> m) & 1u) ? g_overlaps[(b*NM+m)*NA + a] : 0.f;
            if (o > best) { best = o; bi = m; }   // first max kept
        }
        fin = 1u << bi;
    }
    g_finbits[t] = fin;

    int tgt = fin ? (__ffs(fin) - 1) : 0;
    out[FG_OFF + t]  = fin ? 1.f : 0.f;
    out[TGI_OFF + t] = (float)tgt;
    int lbl = gt_labels[b*NM + tgt]; if (lbl < 0) lbl = 0;
    out[TL_OFF + t] = (float)lbl;
    const float4* gb4 = (const float4*)(gt_bboxes);
    ((float4*)(out + TB_OFF))[t] = gb4[b*NM + tgt];

    if (fin) {
        int idx = (b*NM + tgt)*NA + a;
        out[MPB_OFF + idx]  = 1.f;
        out[CENT_OFF + idx] = g_cent[idx];
        const float4* src = (const float4*)(g_dist + (size_t)idx * NBINS);
        float4* dst = (float4*)(out + GTDIST_OFF + (size_t)idx * NBINS);
        #pragma unroll
        for (int e = 0; e < NBINS/4; e++) dst[e] = src[e];
    }
}

// ---------------------------------------------------------------------------
// K5: block-per-GT pos maxima + target_scores; recycles g_cnt to zero
// ---------------------------------------------------------------------------
__global__ __launch_bounds__(256) void k_scores(
    const int* __restrict__ gt_labels,
    float* __restrict__ out)
{
    int bm = blockIdx.x;
    int cnt = g_cnt[bm];
    if (cnt > MAXL) cnt = MAXL;
    int tid = threadIdx.x;
    __shared__ float s1[8], s2[8];
    __shared__ float bpa, bpo;

    if (cnt > 0) {
        int b = bm / NM, m = bm % NM;
        unsigned mybit = 1u << m;
        const int* la = g_liveA + bm*MAXL;

        float pa = 0.f, po = 0.f;
        for (int j = tid; j < cnt; j += 256) {
            int a = la[j];
            if (g_finbits[b*NA + a] == mybit) {
                int idx = bm*NA + a;
                pa = fmaxf(pa, g_align[idx]);
                po = fmaxf(po, g_overlaps[idx]);
            }
        }
        #pragma unroll
        for (int off = 16; off; off >>= 1) {
            pa = fmaxf(pa, __shfl_xor_sync(0xffffffffu, pa, off));
            po = fmaxf(po, __shfl_xor_sync(0xffffffffu, po, off));
        }
        if ((tid & 31) == 0) { s1[tid>>5] = pa; s2[tid>>5] = po; }
        __syncthreads();
        if (tid == 0) {
            float a1 = 0.f, a2 = 0.f;
            #pragma unroll
            for (int w = 0; w < 8; w++) { a1 = fmaxf(a1, s1[w]); a2 = fmaxf(a2, s2[w]); }
            bpa = a1; bpo = a2;
        }
        __syncthreads();

        int lbl = gt_labels[bm]; if (lbl < 0) lbl = 0;
        float A = bpa, O = bpo;
        for (int j = tid; j < cnt; j += 256) {
            int a = la[j];
            int t = b*NA + a;
            if (g_finbits[t] == mybit) {
                float norm = g_align[bm*NA + a] * O / (A + 1e-9f);
                out[TS_OFF + (size_t)t * NC + lbl] = norm;
            }
        }
        __syncthreads();
    }
    if (tid == 0) g_cnt[bm] = 0;        // reset for next replay
}

// ---------------------------------------------------------------------------
extern "C" void kernel_launch(void* const* d_in, const int* in_sizes, int n_in,
                              void* d_out, int out_size) {
    const float* pd_scores = (const float*)d_in[0];
    const float* pd_bboxes = (const float*)d_in[1];
    const float* anc       = (const float*)d_in[2];
    const int*   gt_labels = (const int*)  d_in[3];
    const float* gt_bboxes = (const float*)d_in[4];
    const float* mask_gt   = (const float*)d_in[5];
    const float* gt_coor   = (const float*)d_in[6];
    float* out = (float*)d_out;

    cudaMemsetAsync(out, 0, (size_t)OUT_TOTAL * sizeof(float));
    k_compact<<<(BSNA + 255)/256, 256>>>(anc, gt_bboxes, mask_gt);
    dim3 g1(128, NBM);
    k_pairs<<<g1, 128>>>(pd_scores, pd_bboxes, anc, gt_labels, gt_coor);
    k_topk<<<NBM, 32>>>(mask_gt);
    k_assign<<<(BSNA + 255)/256, 256>>>(gt_labels, gt_bboxes, out);
    k_scores<<<NBM, 256>>>(gt_labels, out);
}

// round 5
// speedup vs baseline: 3.0672x; 3.0672x over previous
#include <cuda_runtime.h>
#include <cuda_bf16.h>
#include <cstdint>

// Problem constants
#define BS     2
#define NM     10
#define NA     8400
#define NC     80
#define NPT    360
#define NBINS  36
#define NBM    (BS*NM)
#define BSNMNA (BS*NM*NA)
#define BSNA   (BS*NA)
#define MAXL   1024
#define FULLM  0xffffffffu

// Output layout (flat float32, reference tuple order)
#define TL_OFF      0
#define TB_OFF      16800
#define TS_OFF      84000
#define MPB_OFF     1428000
#define TGI_OFF     1596000
#define GTDIST_OFF  1612800
#define CENT_OFF    7660800
#define FG_OFF      7828800
#define OUT_TOTAL   7845600

// Scratch. Written at live entries only; read at positive entries (pos ⊆ live).
// g_cnt re-zeroed by k_scores, g_topkbits by k_assign -> replay-invariant.
__device__ float g_align[BSNMNA];
__device__ float g_overlaps[BSNMNA];
__device__ float g_cent[BSNMNA];
__device__ __align__(16) float g_dist[(size_t)BSNMNA * NBINS];
__device__ int   g_liveA[NBM * MAXL];
__device__ int   g_cnt[NBM];
__device__ unsigned g_inbits[BSNA];
__device__ unsigned g_topkbits[BSNA];
__device__ unsigned g_finbits[BSNA];

__device__ __forceinline__ unsigned long long ullmin2(unsigned long long a, unsigned long long b){ return a<b?a:b; }
__device__ __forceinline__ unsigned long long ullmax2(unsigned long long a, unsigned long long b){ return a>b?a:b; }

// ---------------------------------------------------------------------------
// K1: per-anchor in-box bitmask + per-GT compacted live lists
// ---------------------------------------------------------------------------
__global__ __launch_bounds__(256) void k_compact(
    const float* __restrict__ anc,
    const float* __restrict__ gt_bboxes,
    const float* __restrict__ mask_gt)
{
    __shared__ float sbox[NBM][4];
    __shared__ float smgt[NBM];
    if (threadIdx.x < NBM) {
        sbox[threadIdx.x][0] = gt_bboxes[threadIdx.x*4+0];
        sbox[threadIdx.x][1] = gt_bboxes[threadIdx.x*4+1];
        sbox[threadIdx.x][2] = gt_bboxes[threadIdx.x*4+2];
        sbox[threadIdx.x][3] = gt_bboxes[threadIdx.x*4+3];
        smgt[threadIdx.x] = mask_gt[threadIdx.x];
    }
    __syncthreads();
    int t = blockIdx.x * blockDim.x + threadIdx.x;
    if (t >= BSNA) return;
    int b = t / NA, a = t % NA;
    float ax = anc[2*a], ay = anc[2*a+1];
    unsigned inb = 0;
    #pragma unroll
    for (int m = 0; m < NM; m++) {
        int bm = b*NM + m;
        if (smgt[bm] == 0.f) continue;
        float mind = fminf(fminf(ax - sbox[bm][0], ay - sbox[bm][1]),
                           fminf(sbox[bm][2] - ax, sbox[bm][3] - ay));
        if (mind > 1e-9f) {
            inb |= (1u << m);
            int s = atomicAdd(&g_cnt[bm], 1);
            if (s < MAXL) g_liveA[bm*MAXL + s] = a;
        }
    }
    g_inbits[t] = inb;
}

// ---------------------------------------------------------------------------
// K2: heavy per-pair work; bucketed angles + warp-parallel windowed top-4
// ---------------------------------------------------------------------------
__global__ __launch_bounds__(128) void k_pairs(
    const float* __restrict__ pd_scores,
    const float* __restrict__ pd_bboxes,
    const float* __restrict__ anc,
    const int*   __restrict__ gt_labels,
    const float* __restrict__ gt_coor)
{
    int bm = blockIdx.y;
    int cnt = g_cnt[bm];
    if (cnt > MAXL) cnt = MAXL;
    if ((int)blockIdx.x >= cnt) return;      // no work for this block
    int b = bm / NM;

    __shared__ float sx[NPT], sy[NPT], sdist[NPT], sang[NPT], sangC[NPT];
    __shared__ unsigned short sidx[NPT];
    __shared__ unsigned char sbk[NPT];
    __shared__ int scnt[NBINS], scur[NBINS];
    __shared__ int p36[NBINS + 1];
    __shared__ float sdm[NBINS];

    const float* gp = gt_coor + (size_t)bm * (2*NPT);
    for (int p = threadIdx.x; p < NPT; p += blockDim.x) {
        sx[p] = gp[2*p];
        sy[p] = gp[2*p+1];
    }
    int label = gt_labels[bm];
    __syncthreads();

    int tid = threadIdx.x;
    int lane = tid & 31;
    int warp = tid >> 5;

    for (int j = blockIdx.x; j < cnt; j += gridDim.x) {
        int a = g_liveA[bm*MAXL + j];
        float ax = anc[2*a], ay = anc[2*a+1];
        int pairIdx = bm * NA + a;

        if (tid < NBINS) scnt[tid] = 0;
        __syncthreads();

        // point phase: distance + angle + bucket count
        for (int p = tid; p < NPT; p += 128) {
            float dx = sx[p] - ax, dy = sy[p] - ay;
            sdist[p] = sqrtf(dx*dx + dy*dy);
            float ang = atan2f(dy, dx) * 57.29577951308232f;
            if (ang < 0.f) ang += 360.f;
            sang[p] = ang;
            int bk = (int)(ang * 0.1f);
            if (bk > 35) bk = 35;
            sbk[p] = (unsigned char)bk;
            atomicAdd(&scnt[bk], 1);
        }
        __syncthreads();

        // exclusive scan of 36 counts (warp 0) -> p36[0..36]
        if (warp == 0) {
            int orig = (lane < NBINS) ? scnt[lane] : 0;
            int c = orig;
            #pragma unroll
            for (int off = 1; off < 32; off <<= 1) {
                int n = __shfl_up_sync(FULLM, c, off);
                if (lane >= off) c += n;
            }
            int excl = c - orig;
            if (lane < NBINS) { p36[lane] = excl; scur[lane] = excl; }
            int tot32 = __shfl_sync(FULLM, c, 31);
            if (lane < 4) {
                int e = tot32;
                for (int q = 0; q < lane; q++) e += scnt[32+q];
                p36[32+lane] = e; scur[32+lane] = e;
            }
            if (lane == 0) p36[NBINS] = NPT;
        }
        __syncthreads();

        // scatter: angles bucket-contiguous, plus point ids
        for (int p = tid; p < NPT; p += 128) {
            int pos = atomicAdd(&scur[sbk[p]], 1);
            sidx[pos] = (unsigned short)p;
            sangC[pos] = sang[p];
        }
        __syncthreads();

        // bin phase: warp w handles bins w, w+4, ...; whole warp per bin
        for (int bin = warp; bin < NBINS; bin += 4) {
            int binm1 = (bin == 0) ? 35 : bin - 1;
            int c0 = scnt[bin] + scnt[binm1];
            float dm;
            if (c0 == 0) {
                dm = 1e-6f;          // nearest candidate diff >= 10 deg > 3
            } else {
                // find minimal ring L (lane L tests window count >= 4)
                int cntL = 0;
                if (lane < 18) {
                    int loD = bin + 35 - lane;      // doubled-space first bucket
                    int hiD = bin + 36 + lane + 1;  // one past last bucket
                    int addL = 0, xl = loD; while (xl >= NBINS) { xl -= NBINS; addL += NPT; }
                    int addH = 0, xh = hiD; while (xh >= NBINS) { xh -= NBINS; addH += NPT; }
                    cntL = (addH + p36[xh]) - (addL + p36[xl]);
                }
                unsigned ok = __ballot_sync(FULLM, (lane < 18) && (cntL >= 4));
                int L = __ffs(ok) - 1;
                int W = __shfl_sync(FULLM, cntL, L);
                int b0 = bin + 35 - L; while (b0 >= NBINS) b0 -= NBINS;
                int start = p36[b0];
                int W1 = NPT - start; if (W1 > W) W1 = W;   // first CSR segment

                float th = (float)(bin * 10);
                unsigned long long l0=~0ull,l1=~0ull,l2=~0ull,l3=~0ull;
                for (int c = lane; c < W; c += 32) {
                    int pos = (c < W1) ? (start + c) : (c - W1);
                    float df = fabsf(sangC[pos] - th);
                    if (df > 180.f) df = 360.f - df;
                    unsigned long long key =
                        ((unsigned long long)__float_as_uint(df) << 32) | (unsigned)sidx[pos];
                    if (key < l3) {
                        l3 = key;
                        unsigned long long tmp;
                        if (l3 < l2) { tmp=l2; l2=l3; l3=tmp; }
                        if (l2 < l1) { tmp=l1; l1=l2; l2=tmp; }
                        if (l1 < l0) { tmp=l0; l0=l1; l1=tmp; }
                    }
                }
                // 4-round head merge across lanes (keys unique)
                int hp = 0;
                unsigned long long w0,w1,w2,w3;
                #pragma unroll
                for (int r = 0; r < 4; r++) {
                    unsigned long long cand =
                        (hp == 0) ? l0 : (hp == 1) ? l1 : (hp == 2) ? l2 : (hp == 3) ? l3 : ~0ull;
                    unsigned long long m = cand;
                    #pragma unroll
                    for (int off = 16; off; off >>= 1)
                        m = ullmin2(m, __shfl_xor_sync(FULLM, m, off));
                    if (cand == m && m != ~0ull) hp++;
                    if (r == 0) w0 = m; else if (r == 1) w1 = m;
                    else if (r == 2) w2 = m; else w3 = m;
                }
                float mindiff = __uint_as_float((unsigned)(w0 >> 32));
                float dmax = sdist[(unsigned)(w0 & 0xffffffffu)];
                dmax = fmaxf(dmax, sdist[(unsigned)(w1 & 0xffffffffu)]);
                dmax = fmaxf(dmax, sdist[(unsigned)(w2 & 0xffffffffu)]);
                dmax = fmaxf(dmax, sdist[(unsigned)(w3 & 0xffffffffu)]);
                dm = (mindiff > 3.0f) ? 1e-6f : dmax;
                dm = fmaxf(dm, 1e-6f);
            }
            if (lane == 0) {
                sdm[bin] = dm;
                g_dist[(size_t)pairIdx * NBINS + bin] = dm;
            }
        }
        __syncthreads();

        // warp 0 epilogue: iou + centerness + align metric
        if (warp == 0) {
            float smin = 0.f, smax = 0.f, mn = 1e30f, mx = 0.f;
            const float* pb = pd_bboxes + ((size_t)b*NA + a) * NBINS;
            for (int e = lane; e < NBINS; e += 32) {
                float t = sdm[e], p = pb[e];
                smin += fmaxf(fminf(t, p), 1e-6f);
                smax += fmaxf(t, p);
                mn = fminf(mn, t);
                mx = fmaxf(mx, t);
            }
            #pragma unroll
            for (int off = 16; off; off >>= 1) {
                smin += __shfl_xor_sync(FULLM, smin, off);
                smax += __shfl_xor_sync(FULLM, smax, off);
                mn = fminf(mn, __shfl_xor_sync(FULLM, mn, off));
                mx = fmaxf(mx, __shfl_xor_sync(FULLM, mx, off));
            }
            if (lane == 0) {
                float iou = smin / smax;
                float score = pd_scores[((size_t)b*NA + a) * NC + label];
                g_overlaps[pairIdx] = iou;
                g_align[pairIdx]    = score * iou * iou * iou;
                g_cent[pairIdx]     = sqrtf(mn / mx);
            }
        }
        __syncthreads();
    }
}

// ---------------------------------------------------------------------------
// K3: top-13 per GT, single warp, no block barriers
// ---------------------------------------------------------------------------
__global__ __launch_bounds__(32) void k_topk(const float* __restrict__ mask_gt) {
    int bm = blockIdx.x;
    if (mask_gt[bm] == 0.f) return;
    int cnt = g_cnt[bm];
    if (cnt == 0) return;
    if (cnt > MAXL) cnt = MAXL;
    int lane = threadIdx.x;

    __shared__ unsigned long long sk[MAXL];
    const int* la = g_liveA + bm*MAXL;
    for (int j = lane; j < cnt; j += 32) {
        int a = la[j];
        float v = g_align[bm*NA + a];
        sk[j] = ((unsigned long long)__float_as_uint(v) << 32) | (unsigned)(NA - a);
    }
    __syncwarp();

    int b = bm / NM, m = bm % NM;
    int kmax = cnt < 13 ? cnt : 13;
    for (int k = 0; k < kmax; k++) {
        unsigned long long best = 0;
        for (int j = lane; j < cnt; j += 32) best = ullmax2(best, sk[j]);
        #pragma unroll
        for (int off = 16; off; off >>= 1)
            best = ullmax2(best, __shfl_xor_sync(FULLM, best, off));
        if (best == 0) break;   // padding picks carry mask_pos=0 in reference
        for (int j = lane; j < cnt; j += 32) if (sk[j] == best) sk[j] = 0;
        if (lane == 0) {
            int a = NA - (int)(best & 0xffffffffu);
            atomicOr(&g_topkbits[b*NA + a], 1u << m);
        }
        __syncwarp();
    }
}

// ---------------------------------------------------------------------------
// K4: per-anchor resolution + most outputs; recycles g_topkbits to zero
// ---------------------------------------------------------------------------
__global__ __launch_bounds__(128) void k_assign(
    const int*   __restrict__ gt_labels,
    const float* __restrict__ gt_bboxes,
    float* __restrict__ out)
{
    int t = blockIdx.x * blockDim.x + threadIdx.x;
    if (t >= BSNA) return;
    int b = t / NA, a = t % NA;

    unsigned tb = g_topkbits[t];
    g_topkbits[t] = 0u;                 // reset for next replay
    unsigned fin = tb;
    if (__popc(tb) > 1) {
        unsigned inb = g_inbits[t];
        float best = -1.f; int bi = 0;
        #pragma unroll
        for (int m = 0; m < NM; m++) {
            float o = ((inb >> m) & 1u) ? g_overlaps[(b*NM+m)*NA + a] : 0.f;
            if (o > best) { best = o; bi = m; }   // first max kept
        }
        fin = 1u << bi;
    }
    g_finbits[t] = fin;

    int tgt = fin ? (__ffs(fin) - 1) : 0;
    out[FG_OFF + t]  = fin ? 1.f : 0.f;
    out[TGI_OFF + t] = (float)tgt;
    int lbl = gt_labels[b*NM + tgt]; if (lbl < 0) lbl = 0;
    out[TL_OFF + t] = (float)lbl;
    const float4* gb4 = (const float4*)(gt_bboxes);
    ((float4*)(out + TB_OFF))[t] = gb4[b*NM + tgt];

    if (fin) {
        int idx = (b*NM + tgt)*NA + a;
        out[MPB_OFF + idx]  = 1.f;
        out[CENT_OFF + idx] = g_cent[idx];
        const float4* src = (const float4*)(g_dist + (size_t)idx * NBINS);
        float4* dst = (float4*)(out + GTDIST_OFF + (size_t)idx * NBINS);
        #pragma unroll
        for (int e = 0; e < NBINS/4; e++) dst[e] = src[e];
    }
}

// ---------------------------------------------------------------------------
// K5: block-per-GT pos maxima + target_scores; recycles g_cnt to zero
// ---------------------------------------------------------------------------
__global__ __launch_bounds__(256) void k_scores(
    const int* __restrict__ gt_labels,
    float* __restrict__ out)
{
    int bm = blockIdx.x;
    int cnt = g_cnt[bm];
    if (cnt > MAXL) cnt = MAXL;
    int tid = threadIdx.x;
    __shared__ float s1[8], s2[8];
    __shared__ float bpa, bpo;

    if (cnt > 0) {
        int b = bm / NM, m = bm % NM;
        unsigned mybit = 1u << m;
        const int* la = g_liveA + bm*MAXL;

        float pa = 0.f, po = 0.f;
        for (int j = tid; j < cnt; j += 256) {
            int a = la[j];
            if (g_finbits[b*NA + a] == mybit) {
                int idx = bm*NA + a;
                pa = fmaxf(pa, g_align[idx]);
                po = fmaxf(po, g_overlaps[idx]);
            }
        }
        #pragma unroll
        for (int off = 16; off; off >>= 1) {
            pa = fmaxf(pa, __shfl_xor_sync(FULLM, pa, off));
            po = fmaxf(po, __shfl_xor_sync(FULLM, po, off));
        }
        if ((tid & 31) == 0) { s1[tid>>5] = pa; s2[tid>>5] = po; }
        __syncthreads();
        if (tid == 0) {
            float a1 = 0.f, a2 = 0.f;
            #pragma unroll
            for (int w = 0; w < 8; w++) { a1 = fmaxf(a1, s1[w]); a2 = fmaxf(a2, s2[w]); }
            bpa = a1; bpo = a2;
        }
        __syncthreads();

        int lbl = gt_labels[bm]; if (lbl < 0) lbl = 0;
        float A = bpa, O = bpo;
        for (int j = tid; j < cnt; j += 256) {
            int a = la[j];
            int t = b*NA + a;
            if (g_finbits[t] == mybit) {
                float norm = g_align[bm*NA + a] * O / (A + 1e-9f);
                out[TS_OFF + (size_t)t * NC + lbl] = norm;
            }
        }
        __syncthreads();
    }
    if (tid == 0) g_cnt[bm] = 0;        // reset for next replay
}

// ---------------------------------------------------------------------------
extern "C" void kernel_launch(void* const* d_in, const int* in_sizes, int n_in,
                              void* d_out, int out_size) {
    const float* pd_scores = (const float*)d_in[0];
    const float* pd_bboxes = (const float*)d_in[1];
    const float* anc       = (const float*)d_in[2];
    const int*   gt_labels = (const int*)  d_in[3];
    const float* gt_bboxes = (const float*)d_in[4];
    const float* mask_gt   = (const float*)d_in[5];
    const float* gt_coor   = (const float*)d_in[6];
    float* out = (float*)d_out;

    cudaMemsetAsync(out, 0, (size_t)OUT_TOTAL * sizeof(float));
    k_compact<<<(BSNA + 255)/256, 256>>>(anc, gt_bboxes, mask_gt);
    dim3 g1(128, NBM);
    k_pairs<<<g1, 128>>>(pd_scores, pd_bboxes, anc, gt_labels, gt_coor);
    k_topk<<<NBM, 32>>>(mask_gt);
    k_assign<<<(BSNA + 127)/128, 128>>>(gt_labels, gt_bboxes, out);
    k_scores<<<NBM, 256>>>(gt_labels, out);
}